// round 13
// baseline (speedup 1.0000x reference)
#include <cuda_runtime.h>
#include <math.h>

#define NCOLS  16384
#define NT     256
#define V4     (NCOLS / 4 / NT)     // 16 float4 per thread
#define KSEL   256
#define CAP    2048
#define NW     (NT / 32)
#define FTZ    0.75f                // fixed pre-threshold (z units)

__global__ __launch_bounds__(NT, 8)
void entmax_topk_kernel(const float* __restrict__ logits,
                        float* __restrict__ out_w,
                        float* __restrict__ out_cnt)
{
    __shared__ float cand[CAP];
    __shared__ int   cidx[CAP];
    __shared__ float s_f[NW];
    __shared__ int   s_i[NW];
    __shared__ float s_tau, s_th, s_inv;
    __shared__ int   s_useGe;

    const int tid  = threadIdx.x;
    const int lane = tid & 31;
    const int wid  = tid >> 5;
    const int row  = blockIdx.x;

    const float4* src = reinterpret_cast<const float4*>(logits) + (size_t)row * (NCOLS / 4);
    float4*       dst = reinterpret_cast<float4*>(out_w)        + (size_t)row * (NCOLS / 4);

    // ---- Pass A: ONE DRAM sweep = max + count(z > FTZ). No stash, no dyn index. ----
    float lmax = -INFINITY;
    int   lc = 0;
    #pragma unroll 4
    for (int j = 0; j < V4; ++j) {
        float4 t = src[tid + j * NT];               // default policy -> hot in L2
        float zx = 0.5f * t.x, zy = 0.5f * t.y, zz = 0.5f * t.z, zw = 0.5f * t.w;
        lmax = fmaxf(lmax, fmaxf(fmaxf(zx, zy), fmaxf(zz, zw)));
        lc += (zx > FTZ) + (zy > FTZ) + (zz > FTZ) + (zw > FTZ);
    }
    // warp max + warp inclusive scan of counts, published together (one barrier)
    float wm = lmax;
    #pragma unroll
    for (int o = 16; o; o >>= 1) wm = fmaxf(wm, __shfl_xor_sync(0xffffffffu, wm, o));
    int inc = lc;
    #pragma unroll
    for (int o = 1; o < 32; o <<= 1) {
        int t = __shfl_up_sync(0xffffffffu, inc, o);
        if (lane >= o) inc += t;
    }
    if (lane == 0)  s_f[wid] = wm;
    if (lane == 31) s_i[wid] = inc;
    __syncthreads();                                 // barrier 1
    float zmax; int cn, wbase;
    {
        float m = (lane < NW) ? s_f[lane] : -INFINITY;
        #pragma unroll
        for (int o = 4; o; o >>= 1) m = fmaxf(m, __shfl_xor_sync(0xffffffffu, m, o));
        zmax = __shfl_sync(0xffffffffu, m, 0);
        int a = (lane < NW) ? s_i[lane] : 0;
        int sc = a;
        #pragma unroll
        for (int o = 1; o < NW; o <<= 1) {
            int u = __shfl_up_sync(0xffffffffu, sc, o);
            if (lane >= o) sc += u;
        }
        cn    = __shfl_sync(0xffffffffu, sc, NW - 1);
        wbase = __shfl_sync(0xffffffffu, sc - a, wid);
    }
    const float cutoff = zmax - 1.0f;                // rigorous lower bound on tau
    const bool  rowFB  = (cutoff < FTZ);             // block-uniform, rare (~2%)
    float thr = FTZ;
    int   lcf = lc;

    if (rowFB) {                                     // exact recount with true cutoff
        thr = cutoff;
        lcf = 0;
        #pragma unroll 4
        for (int j = 0; j < V4; ++j) {
            float4 t = src[tid + j * NT];            // L2 hit
            lcf += (0.5f * t.x > cutoff) + (0.5f * t.y > cutoff)
                 + (0.5f * t.z > cutoff) + (0.5f * t.w > cutoff);
        }
        int inc2 = lcf;
        #pragma unroll
        for (int o = 1; o < 32; o <<= 1) {
            int t = __shfl_up_sync(0xffffffffu, inc2, o);
            if (lane >= o) inc2 += t;
        }
        __syncthreads();                             // protect s_i reuse
        if (lane == 31) s_i[wid] = inc2;
        __syncthreads();
        int a = (lane < NW) ? s_i[lane] : 0;
        int sc = a;
        #pragma unroll
        for (int o = 1; o < NW; o <<= 1) {
            int u = __shfl_up_sync(0xffffffffu, sc, o);
            if (lane >= o) sc += u;
        }
        cn    = __shfl_sync(0xffffffffu, sc, NW - 1);
        wbase = __shfl_sync(0xffffffffu, sc - a, wid);
        inc = inc2;
    }

    const bool useCand = (cn <= CAP);
    if (useCand) {
        // ---- compact (z, idx) for z > thr; re-read own elements (shortest reuse) ----
        if (lcf > 0) {
            int o = wbase + (inc - lcf);
            #pragma unroll 4
            for (int j = 0; j < V4; ++j) {
                float4 t = src[tid + j * NT];        // L2 hit
                const int base = 4 * (tid + j * NT);
                float z;
                z = 0.5f * t.x; if (z > thr) { cand[o] = z; cidx[o] = base;     ++o; }
                z = 0.5f * t.y; if (z > thr) { cand[o] = z; cidx[o] = base + 1; ++o; }
                z = 0.5f * t.z; if (z > thr) { cand[o] = z; cidx[o] = base + 2; ++o; }
                z = 0.5f * t.w; if (z > thr) { cand[o] = z; cidx[o] = base + 3; ++o; }
            }
        }
        // ---- zero-fill output: write-only stream, drains during the solve ----
        const float4 zer = make_float4(0.f, 0.f, 0.f, 0.f);
        #pragma unroll 4
        for (int j = 0; j < V4; ++j) __stcs(&dst[tid + j * NT], zer);
    }
    __syncthreads();                                 // barrier 2

    // ---- warp 0: solve tau/th/inv AND num_selected ----
    if (wid == 0) {
        const float* cb = useCand ? cand : (logits + (size_t)row * NCOLS);
        const float  sc = useCand ? 1.0f : 0.5f;
        const int    n  = useCand ? cn : NCOLS;
        float tau = cutoff, th, inv;
        int useGe = 0, sel = 0;

        if (useCand && cn <= 256) {                  // reg-cache path (rowFB rows)
            float rv[8];
            #pragma unroll
            for (int r = 0; r < 8; ++r) {
                int idx = r * 32 + lane;
                rv[r] = (idx < cn) ? cand[idx] : -1e30f;
            }
            float gfin = 0.f;
            for (int it = 0; it < 24; ++it) {
                float g = 0.f, gp = 0.f;
                #pragma unroll
                for (int r = 0; r < 8; ++r) {
                    float d = rv[r] - tau;
                    if (d > 0.f) { g = fmaf(d, d, g); gp += d; }
                }
                #pragma unroll
                for (int o = 16; o; o >>= 1) {
                    g  += __shfl_xor_sync(0xffffffffu, g,  o);
                    gp += __shfl_xor_sync(0xffffffffu, gp, o);
                }
                gfin = g;
                g -= 1.0f;
                if (gp <= 0.f) break;
                float step = g / (2.0f * gp);
                tau += step;
                if (step < 1e-7f) break;
            }
            int S = 0;
            #pragma unroll
            for (int r = 0; r < 8; ++r) S += (rv[r] > tau) ? 1 : 0;
            #pragma unroll
            for (int o = 16; o; o >>= 1) S += __shfl_xor_sync(0xffffffffu, S, o);
            th = tau;
            float ssum = gfin;
            if (S > KSEL) {
                useGe = 1;
                float lo = tau, hi = zmax;
                for (int it = 0; it < 48; ++it) {
                    float mid = 0.5f * (lo + hi);
                    int c = 0;
                    #pragma unroll
                    for (int r = 0; r < 8; ++r) c += (rv[r] >= mid) ? 1 : 0;
                    #pragma unroll
                    for (int o = 16; o; o >>= 1) c += __shfl_xor_sync(0xffffffffu, c, o);
                    if (c >= KSEL) lo = mid; else hi = mid;
                }
                th = lo;
                ssum = 0.f;
                #pragma unroll
                for (int r = 0; r < 8; ++r) {
                    float z = rv[r], d = z - tau;
                    if (z >= th && d > 0.f) ssum = fmaf(d, d, ssum);
                }
                #pragma unroll
                for (int o = 16; o; o >>= 1) ssum += __shfl_xor_sync(0xffffffffu, ssum, o);
            }
            inv = 1.0f / (ssum + 1e-8f);
            #pragma unroll
            for (int r = 0; r < 8; ++r) {
                float z = rv[r], d = z - tau;
                bool keep = useGe ? (z >= th && d > 0.f) : (d > 0.f);
                float w = keep ? d * d * inv : 0.f;
                sel += (w > 1e-6f);
            }
        } else {
            // generic: coalesced LDS over superset (or global row on overflow)
            float gfin = 0.f;
            for (int it = 0; it < 24; ++it) {
                float g = 0.f, gp = 0.f;
                for (int i = lane; i < n; i += 32) {
                    float d = sc * cb[i] - tau;
                    if (d > 0.f) { g = fmaf(d, d, g); gp += d; }
                }
                #pragma unroll
                for (int o = 16; o; o >>= 1) {
                    g  += __shfl_xor_sync(0xffffffffu, g,  o);
                    gp += __shfl_xor_sync(0xffffffffu, gp, o);
                }
                gfin = g;
                g -= 1.0f;
                if (gp <= 0.f) break;
                float step = g / (2.0f * gp);
                tau += step;
                if (step < 1e-7f) break;
            }
            int S = 0;
            for (int i = lane; i < n; i += 32) S += (sc * cb[i] > tau) ? 1 : 0;
            #pragma unroll
            for (int o = 16; o; o >>= 1) S += __shfl_xor_sync(0xffffffffu, S, o);
            th = tau;
            float ssum = gfin;
            if (S > KSEL) {
                useGe = 1;
                float lo = tau, hi = zmax;
                for (int it = 0; it < 48; ++it) {
                    float mid = 0.5f * (lo + hi);
                    int c = 0;
                    for (int i = lane; i < n; i += 32) c += (sc * cb[i] >= mid) ? 1 : 0;
                    #pragma unroll
                    for (int o = 16; o; o >>= 1) c += __shfl_xor_sync(0xffffffffu, c, o);
                    if (c >= KSEL) lo = mid; else hi = mid;
                }
                th = lo;
                ssum = 0.f;
                for (int i = lane; i < n; i += 32) {
                    float z = sc * cb[i], d = z - tau;
                    if (z >= th && d > 0.f) ssum = fmaf(d, d, ssum);
                }
                #pragma unroll
                for (int o = 16; o; o >>= 1) ssum += __shfl_xor_sync(0xffffffffu, ssum, o);
            }
            inv = 1.0f / (ssum + 1e-8f);
            for (int i = lane; i < n; i += 32) {
                float z = sc * cb[i], d = z - tau;
                bool keep = useGe ? (z >= th && d > 0.f) : (d > 0.f);
                float w = keep ? d * d * inv : 0.f;
                sel += (w > 1e-6f);
            }
        }
        #pragma unroll
        for (int o = 16; o; o >>= 1) sel += __shfl_xor_sync(0xffffffffu, sel, o);
        if (lane == 0) {
            s_tau = tau; s_th = th; s_useGe = useGe; s_inv = inv;
            out_cnt[row] = (float)sel;
        }
    }
    __syncthreads();                                 // barrier 3 (last)

    const float tau = s_tau, th = s_th, inv = s_inv;
    const bool  useGe = (s_useGe != 0);

    if (useCand) {
        // ---- scatter the (at most cn) nonzero weights over the zero-filled row ----
        float* orow = out_w + (size_t)row * NCOLS;
        for (int i = tid; i < cn; i += NT) {
            float z = cand[i], d = z - tau;
            bool keep = useGe ? (z >= th && d > 0.f) : (d > 0.f);
            orow[cidx[i]] = keep ? d * d * inv : 0.f;
        }
    } else {
        // adversarial fallback: full output stream from global
        #pragma unroll 4
        for (int j = 0; j < V4; ++j) {
            float4 t = src[tid + j * NT];
            float4 w;
            {
                float z = 0.5f * t.x, d = z - tau;
                bool keep = useGe ? (z >= th && d > 0.f) : (d > 0.f);
                w.x = keep ? d * d * inv : 0.f;
            }
            {
                float z = 0.5f * t.y, d = z - tau;
                bool keep = useGe ? (z >= th && d > 0.f) : (d > 0.f);
                w.y = keep ? d * d * inv : 0.f;
            }
            {
                float z = 0.5f * t.z, d = z - tau;
                bool keep = useGe ? (z >= th && d > 0.f) : (d > 0.f);
                w.z = keep ? d * d * inv : 0.f;
            }
            {
                float z = 0.5f * t.w, d = z - tau;
                bool keep = useGe ? (z >= th && d > 0.f) : (d > 0.f);
                w.w = keep ? d * d * inv : 0.f;
            }
            __stcs(&dst[tid + j * NT], w);
        }
    }
}

extern "C" void kernel_launch(void* const* d_in, const int* in_sizes, int n_in,
                              void* d_out, int out_size)
{
    const float* logits = (const float*)d_in[0];
    float* out = (float*)d_out;
    const int B = in_sizes[0] / NCOLS;
    entmax_topk_kernel<<<B, NT>>>(logits, out, out + (size_t)B * NCOLS);
}